// round 1
// baseline (speedup 1.0000x reference)
#include <cuda_runtime.h>
#include <math.h>

#define NN 100000
#define EE 1600000
#define FF 128
#define CC 256

// ---------------- static scratch (no allocations allowed) ----------------
__device__ int   g_deg[2][NN];
__device__ int   g_off[2][NN];
__device__ int   g_cur[2][NN];
__device__ float g_inv[2][NN];
__device__ int   g_esrc[2][EE];
__device__ float g_mx[2][(size_t)NN * FF];   // layer-0 means (128-d)
__device__ float g_h1[2][(size_t)NN * CC];   // layer-0 outputs A1,B1
__device__ float g_m1[2][(size_t)NN * CC];   // layer-1 means (256-d)
__device__ float g_wf[4][FF * CC];           // fused input-proj weights

// ---------------- CSR build ----------------
__global__ void k_zero(int* p, int n) {
    int i = blockIdx.x * blockDim.x + threadIdx.x;
    if (i < n) p[i] = 0;
}

__global__ void k_count(const int* __restrict__ dst, int* __restrict__ deg) {
    int i = blockIdx.x * blockDim.x + threadIdx.x;
    if (i < EE) atomicAdd(&deg[dst[i]], 1);
}

// one block per edge type: exclusive scan of degrees -> offsets, cursors, 1/deg
__global__ void k_scan() {
    int t = blockIdx.x;
    __shared__ int sh[1024];
    __shared__ int carry;
    if (threadIdx.x == 0) carry = 0;
    __syncthreads();
    for (int base = 0; base < NN; base += 1024) {
        int i = base + threadIdx.x;
        int v = (i < NN) ? g_deg[t][i] : 0;
        sh[threadIdx.x] = v;
        __syncthreads();
        for (int o = 1; o < 1024; o <<= 1) {
            int y = (threadIdx.x >= o) ? sh[threadIdx.x - o] : 0;
            __syncthreads();
            sh[threadIdx.x] += y;
            __syncthreads();
        }
        int excl = carry + sh[threadIdx.x] - v;
        if (i < NN) {
            g_off[t][i] = excl;
            g_cur[t][i] = excl;
            g_inv[t][i] = (v > 0) ? 1.0f / (float)v : 0.0f;
        }
        __syncthreads();
        if (threadIdx.x == 0) carry += sh[1023];
        __syncthreads();
    }
}

__global__ void k_fill(const int* __restrict__ src, const int* __restrict__ dst,
                       int* __restrict__ cur, int* __restrict__ esrc) {
    int i = blockIdx.x * blockDim.x + threadIdx.x;
    if (i < EE) {
        int d = dst[i];
        int p = atomicAdd(&cur[d], 1);
        esrc[p] = src[i];
    }
}

// ---------------- segment mean gather (warp per dst node) ----------------
template <int DIM>
__global__ void k_agg(const float* __restrict__ feat, const int* __restrict__ esrc,
                      const int* __restrict__ off, const int* __restrict__ deg,
                      const float* __restrict__ inv, float* __restrict__ out) {
    int w = (blockIdx.x * blockDim.x + threadIdx.x) >> 5;
    if (w >= NN) return;
    int lane = threadIdx.x & 31;
    const int V = DIM / 128;  // float4 per lane
    float4 acc[V];
#pragma unroll
    for (int v = 0; v < V; v++) acc[v] = make_float4(0.f, 0.f, 0.f, 0.f);
    int s0 = off[w], d = deg[w];
    int k = 0;
    for (; k + 2 <= d; k += 2) {  // 2 rows in flight for MLP
        int sA = esrc[s0 + k], sB = esrc[s0 + k + 1];
        const float4* ra = (const float4*)(feat + (size_t)sA * DIM);
        const float4* rb = (const float4*)(feat + (size_t)sB * DIM);
#pragma unroll
        for (int v = 0; v < V; v++) {
            float4 a = ra[lane + 32 * v];
            float4 b = rb[lane + 32 * v];
            acc[v].x += a.x + b.x; acc[v].y += a.y + b.y;
            acc[v].z += a.z + b.z; acc[v].w += a.w + b.w;
        }
    }
    if (k < d) {
        int sA = esrc[s0 + k];
        const float4* ra = (const float4*)(feat + (size_t)sA * DIM);
#pragma unroll
        for (int v = 0; v < V; v++) {
            float4 a = ra[lane + 32 * v];
            acc[v].x += a.x; acc[v].y += a.y; acc[v].z += a.z; acc[v].w += a.w;
        }
    }
    float iv = inv[w];
    float4* o = (float4*)(out + (size_t)w * DIM);
#pragma unroll
    for (int v = 0; v < V; v++)
        o[lane + 32 * v] = make_float4(acc[v].x * iv, acc[v].y * iv,
                                       acc[v].z * iv, acc[v].w * iv);
}

// ---------------- dual-input SGEMM: out = A0@W0 + A1@W1 + b0 (+b1), opt sigmoid ----
// N fixed = 256 columns. Block tile 128x128, BK=16, 256 threads, 8x8 per thread.
__global__ __launch_bounds__(256, 2) void k_gemm(
    const float* __restrict__ A0, const float* __restrict__ W0, int K0,
    const float* __restrict__ A1p, const float* __restrict__ W1, int K1,
    const float* __restrict__ b0, const float* __restrict__ b1,
    float* __restrict__ out, int M, int act) {
    __shared__ float As[16][128];
    __shared__ float Bs[16][128];
    int tid = threadIdx.x;
    int tx = tid & 15, ty = tid >> 4;
    int m0 = blockIdx.x * 128, n0 = blockIdx.y * 128;

    float acc[8][8];
#pragma unroll
    for (int i = 0; i < 8; i++)
#pragma unroll
        for (int j = 0; j < 8; j++) acc[i][j] = 0.f;

    for (int ph = 0; ph < 2; ph++) {
        const float* Ap = ph ? A1p : A0;
        const float* Wp = ph ? W1 : W0;
        int K = ph ? K1 : K0;
        if (K == 0 || Ap == nullptr) continue;
        for (int kk = 0; kk < K; kk += 16) {
            // A tile (128 rows x 16 k), transposed into As[k][m]
#pragma unroll
            for (int l = 0; l < 2; l++) {
                int f4 = tid * 2 + l;
                int row = f4 >> 2, c4 = f4 & 3;
                float4 v = make_float4(0.f, 0.f, 0.f, 0.f);
                int gr = m0 + row;
                if (gr < M) v = *(const float4*)(Ap + (size_t)gr * K + kk + c4 * 4);
                As[c4 * 4 + 0][row] = v.x;
                As[c4 * 4 + 1][row] = v.y;
                As[c4 * 4 + 2][row] = v.z;
                As[c4 * 4 + 3][row] = v.w;
            }
            // B tile (16 k x 128 n)
#pragma unroll
            for (int l = 0; l < 2; l++) {
                int f4 = tid * 2 + l;
                int r = f4 >> 5, c4 = f4 & 31;
                *(float4*)&Bs[r][c4 * 4] =
                    *(const float4*)(Wp + (size_t)(kk + r) * CC + n0 + c4 * 4);
            }
            __syncthreads();
#pragma unroll
            for (int k = 0; k < 16; k++) {
                float a[8], b[8];
                *(float4*)(a)     = *(float4*)&As[k][ty * 8];
                *(float4*)(a + 4) = *(float4*)&As[k][ty * 8 + 4];
                *(float4*)(b)     = *(float4*)&Bs[k][tx * 8];
                *(float4*)(b + 4) = *(float4*)&Bs[k][tx * 8 + 4];
#pragma unroll
                for (int i = 0; i < 8; i++)
#pragma unroll
                    for (int j = 0; j < 8; j++) acc[i][j] += a[i] * b[j];
            }
            __syncthreads();
        }
    }

    float bias[8];
#pragma unroll
    for (int j = 0; j < 8; j++) {
        int c = n0 + tx * 8 + j;
        float bv = b0 ? b0[c] : 0.f;
        if (b1) bv += b1[c];
        bias[j] = bv;
    }
#pragma unroll
    for (int i = 0; i < 8; i++) {
        int gr = m0 + ty * 8 + i;
        if (gr >= M) continue;
        float vals[8];
#pragma unroll
        for (int j = 0; j < 8; j++) {
            float v = acc[i][j] + bias[j];
            if (act) v = 1.0f / (1.0f + __expf(-v));
            vals[j] = v;
        }
        float* op = out + (size_t)gr * CC + n0 + tx * 8;
        *(float4*)(op)     = *(float4*)(vals);
        *(float4*)(op + 4) = *(float4*)(vals + 4);
    }
}

// ---------------- host orchestration ----------------
extern "C" void kernel_launch(void* const* d_in, const int* in_sizes, int n_in,
                              void* d_out, int out_size) {
    const float* x_A    = (const float*)d_in[0];
    const float* x_B    = (const float*)d_in[1];
    const int*   e_ab   = (const int*)d_in[4];   // [2,E] src,dst  A->B
    const int*   e_ba   = (const int*)d_in[5];   // [2,E]          B->A
    const float* lin_A  = (const float*)d_in[6];
    const float* lin_B  = (const float*)d_in[7];
    const float* bias_A = (const float*)d_in[8];
    const float* bias_B = (const float*)d_in[9];
    const float* Wl_ab0 = (const float*)d_in[10];
    const float* bl_ab0 = (const float*)d_in[11];
    const float* Wr_ab0 = (const float*)d_in[12];
    const float* Wl_ba0 = (const float*)d_in[13];
    const float* bl_ba0 = (const float*)d_in[14];
    const float* Wr_ba0 = (const float*)d_in[15];
    const float* Wl_ab1 = (const float*)d_in[16];
    const float* bl_ab1 = (const float*)d_in[17];
    const float* Wr_ab1 = (const float*)d_in[18];
    const float* Wl_ba1 = (const float*)d_in[19];
    const float* bl_ba1 = (const float*)d_in[20];
    const float* Wr_ba1 = (const float*)d_in[21];
    float* out = (float*)d_out;

    int *deg, *off, *cur, *esrc;
    float *inv, *mx, *h1, *m1, *wf;
    cudaGetSymbolAddress((void**)&deg, g_deg);
    cudaGetSymbolAddress((void**)&off, g_off);
    cudaGetSymbolAddress((void**)&cur, g_cur);
    cudaGetSymbolAddress((void**)&inv, g_inv);
    cudaGetSymbolAddress((void**)&esrc, g_esrc);
    cudaGetSymbolAddress((void**)&mx, g_mx);
    cudaGetSymbolAddress((void**)&h1, g_h1);
    cudaGetSymbolAddress((void**)&m1, g_m1);
    cudaGetSymbolAddress((void**)&wf, g_wf);

    int* deg0 = deg;            int* deg1 = deg + NN;
    int* off0 = off;            int* off1 = off + NN;
    int* cur0 = cur;            int* cur1 = cur + NN;
    float* inv0 = inv;          float* inv1 = inv + NN;
    int* esrc0 = esrc;          int* esrc1 = esrc + EE;
    float* mx0 = mx;            float* mx1 = mx + (size_t)NN * FF;
    float* h1A = h1;            float* h1B = h1 + (size_t)NN * CC;
    float* m1A = m1;            float* m1B = m1 + (size_t)NN * CC;
    float* wf0 = wf;            // lin_B @ Wl_ba0
    float* wf1 = wf + FF * CC;      // lin_A @ Wr_ba0
    float* wf2 = wf + 2 * FF * CC;  // lin_A @ Wl_ab0
    float* wf3 = wf + 3 * FF * CC;  // lin_B @ Wr_ab0

    const int TB = 256;
    int gE = (EE + TB - 1) / TB;
    int gAgg = (NN * 32 + TB - 1) / TB;
    dim3 gW(1, 2);                       // 128-row fused-weight GEMMs
    dim3 gM((NN + 127) / 128, 2);        // main GEMMs

    // CSR build (type 0 = ba edges -> dst A, type 1 = ab edges -> dst B)
    k_zero<<<(2 * NN + TB - 1) / TB, TB>>>(deg, 2 * NN);
    k_count<<<gE, TB>>>(e_ba + EE, deg0);
    k_count<<<gE, TB>>>(e_ab + EE, deg1);
    k_scan<<<2, 1024>>>();
    k_fill<<<gE, TB>>>(e_ba, e_ba + EE, cur0, esrc0);
    k_fill<<<gE, TB>>>(e_ab, e_ab + EE, cur1, esrc1);

    // fused weights: fold input projections into SAGE layer-0 weights
    k_gemm<<<gW, TB>>>(lin_B, Wl_ba0, CC, nullptr, nullptr, 0, nullptr, nullptr, wf0, FF, 0);
    k_gemm<<<gW, TB>>>(lin_A, Wr_ba0, CC, nullptr, nullptr, 0, nullptr, nullptr, wf1, FF, 0);
    k_gemm<<<gW, TB>>>(lin_A, Wl_ab0, CC, nullptr, nullptr, 0, nullptr, nullptr, wf2, FF, 0);
    k_gemm<<<gW, TB>>>(lin_B, Wr_ab0, CC, nullptr, nullptr, 0, nullptr, nullptr, wf3, FF, 0);

    // layer-0 aggregation at 128 dims (raw features)
    k_agg<128><<<gAgg, TB>>>(x_B, esrc0, off0, deg0, inv0, mx0);
    k_agg<128><<<gAgg, TB>>>(x_A, esrc1, off1, deg1, inv1, mx1);

    // layer 0: A1 = mean_ba(x_B)@wf0 + x_A@wf1 + bl_ba0 ; B1 analogous
    k_gemm<<<gM, TB>>>(mx0, wf0, FF, x_A, wf1, FF, bl_ba0, nullptr, h1A, NN, 0);
    k_gemm<<<gM, TB>>>(mx1, wf2, FF, x_B, wf3, FF, bl_ab0, nullptr, h1B, NN, 0);

    // layer-1 aggregation at 256 dims
    k_agg<256><<<gAgg, TB>>>(h1B, esrc0, off0, deg0, inv0, m1A);
    k_agg<256><<<gAgg, TB>>>(h1A, esrc1, off1, deg1, inv1, m1B);

    // layer 1 + final bias + sigmoid, straight into d_out
    k_gemm<<<gM, TB>>>(m1A, Wl_ba1, CC, h1A, Wr_ba1, CC, bl_ba1, bias_A, out, NN, 1);
    k_gemm<<<gM, TB>>>(m1B, Wl_ab1, CC, h1B, Wr_ab1, CC, bl_ab1, bias_B,
                       out + (size_t)NN * CC, NN, 1);
}

// round 3
// speedup vs baseline: 1.8694x; 1.8694x over previous
#include <cuda_runtime.h>
#include <cuda_bf16.h>
#include <cstdint>
#include <math.h>

#define NN 100000
#define EE 1600000
#define FF 128
#define CC 256

// Detect whether this device-compilation pass has tcgen05 (sm_103a/sm_100a or family target).
#if defined(__CUDA_ARCH_FEAT_SM103_ALL) || defined(__CUDA_ARCH_FEAT_SM100_ALL)
#define HAS_TCGEN05 1
#elif defined(__CUDA_ARCH_SPECIFIC__) && (__CUDA_ARCH_SPECIFIC__ >= 1000)
#define HAS_TCGEN05 1
#elif defined(__CUDA_ARCH_FAMILY_SPECIFIC__) && (__CUDA_ARCH_FAMILY_SPECIFIC__ >= 1000)
#define HAS_TCGEN05 1
#else
#define HAS_TCGEN05 0
#endif

// ---------------- static scratch (no allocations allowed) ----------------
__device__ int   g_deg[2][NN];
__device__ int   g_off[2][NN];
__device__ int   g_cur[2][NN];
__device__ float g_inv[2][NN];
__device__ int   g_tot[2];
__device__ int   g_esrc[2][EE];
__device__ float g_mx[2][(size_t)NN * FF];     // layer-0 means (128-d)
__device__ float g_h1[2][(size_t)NN * CC];     // layer-0 outputs A1,B1
__device__ float g_m1[2][(size_t)NN * CC];     // layer-1 means (256-d)
// transposed + bf16 hi/lo split weights, [N][K] K-major
__device__ __nv_bfloat16 g_w0[4][2][256 * 128];  // layer-0 fused weights (K=128)
__device__ __nv_bfloat16 g_w1[4][2][256 * 256];  // layer-1 weights (K=256)

// ================= PTX helpers =================
__device__ __forceinline__ uint32_t smem_u32(const void* p) {
    uint32_t a;
    asm("{ .reg .u64 t; cvta.to.shared.u64 t, %1; cvt.u32.u64 %0, t; }"
        : "=r"(a) : "l"(p));
    return a;
}

#if HAS_TCGEN05
__device__ __forceinline__ uint32_t elect_one_pred() {
    uint32_t p;
    asm volatile("{\n\t.reg .pred p;\n\telect.sync _|p, 0xFFFFFFFF;\n\t"
                 "selp.b32 %0, 1, 0, p;\n\t}" : "=r"(p));
    return p;
}
#define MBARRIER_INIT(a, c) \
    asm volatile("mbarrier.init.shared.b64 [%0], %1;" :: "r"((uint32_t)(a)), "r"((uint32_t)(c)) : "memory")
#define MBARRIER_WAIT_PARITY(a, ph) do { \
    uint32_t _m = (uint32_t)(a), _p = (uint32_t)(ph), _d; \
    asm volatile("{\n\t.reg .pred p;\n\t" \
        "mbarrier.try_wait.parity.acquire.cta.shared::cta.b64 p, [%1], %2;\n\t" \
        "selp.b32 %0, 1, 0, p;\n\t}" : "=r"(_d) : "r"(_m), "r"(_p) : "memory"); \
    if (!_d) { \
        asm volatile("{\n\t.reg .pred P1;\n\tWL_%=:\n\t" \
            "mbarrier.try_wait.parity.acquire.cta.shared::cta.b64 P1, [%0], %1, 0x989680;\n\t" \
            "@P1 bra.uni WD_%=;\n\tbra.uni WL_%=;\n\tWD_%=:\n\t}" \
            :: "r"(_m), "r"(_p) : "memory"); \
    } } while (0)
#define TCGEN05_ALLOC(sa, n) \
    asm volatile("tcgen05.alloc.cta_group::1.sync.aligned.shared::cta.b32 [%0], %1;" \
                 :: "r"((uint32_t)(sa)), "r"((uint32_t)(n)) : "memory")
#define TCGEN05_DEALLOC(t, n) \
    asm volatile("tcgen05.dealloc.cta_group::1.sync.aligned.b32 %0, %1;" :: "r"(t), "r"((uint32_t)(n)))
#define TCGEN05_RELINQ() \
    asm volatile("tcgen05.relinquish_alloc_permit.cta_group::1.sync.aligned;")
#define TCGEN05_COMMIT(a) \
    asm volatile("tcgen05.commit.cta_group::1.mbarrier::arrive::one.shared::cluster.b64 [%0];" \
                 :: "r"((uint32_t)(a)) : "memory")
#define TCGEN05_FENCE_AFTER() asm volatile("tcgen05.fence::after_thread_sync;" ::: "memory")
#define TCGEN05_FENCE_BEFORE() asm volatile("tcgen05.fence::before_thread_sync;" ::: "memory")
#define TCGEN05_WAIT_LD() asm volatile("tcgen05.wait::ld.sync.aligned;" ::: "memory")
#define FENCE_PROXY_ASYNC() asm volatile("fence.proxy.async.shared::cta;" ::: "memory")
#define TCGEN05_LD_X32(r, a) \
    asm volatile("tcgen05.ld.sync.aligned.32x32b.x32.b32 " \
        "{%0, %1, %2, %3, %4, %5, %6, %7, %8, %9, %10, %11, %12, %13, %14, %15, " \
        "%16, %17, %18, %19, %20, %21, %22, %23, %24, %25, %26, %27, %28, %29, %30, %31}, [%32];" \
        : "=r"((r)[0]), "=r"((r)[1]), "=r"((r)[2]), "=r"((r)[3]), "=r"((r)[4]), "=r"((r)[5]), \
          "=r"((r)[6]), "=r"((r)[7]), "=r"((r)[8]), "=r"((r)[9]), "=r"((r)[10]), "=r"((r)[11]), \
          "=r"((r)[12]), "=r"((r)[13]), "=r"((r)[14]), "=r"((r)[15]), "=r"((r)[16]), "=r"((r)[17]), \
          "=r"((r)[18]), "=r"((r)[19]), "=r"((r)[20]), "=r"((r)[21]), "=r"((r)[22]), "=r"((r)[23]), \
          "=r"((r)[24]), "=r"((r)[25]), "=r"((r)[26]), "=r"((r)[27]), "=r"((r)[28]), "=r"((r)[29]), \
          "=r"((r)[30]), "=r"((r)[31]) : "r"(a))

static constexpr uint64_t SMEM_DESC_BASE_SW128 =
    (uint64_t(2) << 61) | (uint64_t(1) << 46) | (uint64_t(64) << 32) | (uint64_t(1) << 16);
#define MAKE_SMEM_DESC(a) (SMEM_DESC_BASE_SW128 | ((uint64_t)((a) >> 4) & 0x3FFF))

// idesc kind::f16: dtype=F32(1<<4), atype=BF16(1<<7), btype=BF16(1<<10), N=128, M=128
#define IDESC ((1u << 4) | (1u << 7) | (1u << 10) | (16u << 17) | (8u << 24))

__device__ __forceinline__ void mma_f16_ss(uint32_t d, uint64_t ad, uint64_t bd, bool acc) {
    uint32_t en = acc ? 1u : 0u, z = 0u;
    asm volatile("{\n\t.reg .pred p;\n\tsetp.ne.u32 p, %5, 0;\n\t"
        "tcgen05.mma.cta_group::1.kind::f16 [%0], %1, %2, %3, {%4, %4, %4, %4}, p;\n\t}"
        :: "r"(d), "l"(ad), "l"(bd), "r"(IDESC), "r"(z), "r"(en) : "memory");
}
#endif  // HAS_TCGEN05

// ---------------- CSR build ----------------
__global__ void k_count(const int* __restrict__ dst, int* __restrict__ deg) {
    int i = blockIdx.x * blockDim.x + threadIdx.x;
    if (i < EE) atomicAdd(&deg[dst[i]], 1);
}
// order-free offset allocation (mean aggregation is order-invariant)
__global__ void k_alloc() {
    int i = blockIdx.x * blockDim.x + threadIdx.x;
    if (i >= 2 * NN) return;
    int t = i / NN, j = i - t * NN;
    int d = g_deg[t][j];
    int o = atomicAdd(&g_tot[t], d);
    g_off[t][j] = o;
    g_cur[t][j] = o;
    g_inv[t][j] = (d > 0) ? 1.0f / (float)d : 0.0f;
}
__global__ void k_fill(const int* __restrict__ src, const int* __restrict__ dst,
                       int* __restrict__ cur, int* __restrict__ esrc) {
    int i = blockIdx.x * blockDim.x + threadIdx.x;
    if (i < EE) {
        int d = dst[i];
        int p = atomicAdd(&cur[d], 1);
        esrc[p] = src[i];
    }
}

// ---------------- segment mean gather (warp per dst node) ----------------
template <int DIM>
__global__ void k_agg(const float* __restrict__ feat, const int* __restrict__ esrc,
                      const int* __restrict__ off, const int* __restrict__ deg,
                      const float* __restrict__ inv, float* __restrict__ out) {
    int w = (blockIdx.x * blockDim.x + threadIdx.x) >> 5;
    if (w >= NN) return;
    int lane = threadIdx.x & 31;
    const int V = DIM / 128;
    float4 acc[V];
#pragma unroll
    for (int v = 0; v < V; v++) acc[v] = make_float4(0.f, 0.f, 0.f, 0.f);
    int s0 = off[w], d = deg[w];
    int k = 0;
    for (; k + 2 <= d; k += 2) {
        int sA = esrc[s0 + k], sB = esrc[s0 + k + 1];
        const float4* ra = (const float4*)(feat + (size_t)sA * DIM);
        const float4* rb = (const float4*)(feat + (size_t)sB * DIM);
#pragma unroll
        for (int v = 0; v < V; v++) {
            float4 a = ra[lane + 32 * v];
            float4 b = rb[lane + 32 * v];
            acc[v].x += a.x + b.x; acc[v].y += a.y + b.y;
            acc[v].z += a.z + b.z; acc[v].w += a.w + b.w;
        }
    }
    if (k < d) {
        int sA = esrc[s0 + k];
        const float4* ra = (const float4*)(feat + (size_t)sA * DIM);
#pragma unroll
        for (int v = 0; v < V; v++) {
            float4 a = ra[lane + 32 * v];
            acc[v].x += a.x; acc[v].y += a.y; acc[v].z += a.z; acc[v].w += a.w;
        }
    }
    float iv = inv[w];
    float4* o = (float4*)(out + (size_t)w * DIM);
#pragma unroll
    for (int v = 0; v < V; v++)
        o[lane + 32 * v] = make_float4(acc[v].x * iv, acc[v].y * iv,
                                       acc[v].z * iv, acc[v].w * iv);
}

// ---------------- weight prep ----------------
__device__ __forceinline__ void split_store(__nv_bfloat16* oh, __nv_bfloat16* ol,
                                            size_t idx, float v) {
    __nv_bfloat16 h = __float2bfloat16_rn(v);
    float r = v - __bfloat162float(h);
    oh[idx] = h;
    ol[idx] = __float2bfloat16_rn(r);
}

// wfT[n][k] = sum_c lin[k][c] * W[c][n], output [256][128] bf16 hi/lo
__global__ void k_fusew(const float* __restrict__ lin, const float* __restrict__ W,
                        __nv_bfloat16* __restrict__ oh, __nv_bfloat16* __restrict__ ol) {
    int k = blockIdx.x;        // 0..127
    int n = threadIdx.x;       // 0..255
    __shared__ float lk[256];
    lk[n] = lin[k * 256 + n];
    __syncthreads();
    float acc = 0.f;
#pragma unroll 8
    for (int c = 0; c < 256; c++) acc += lk[c] * W[c * 256 + n];
    split_store(oh, ol, (size_t)n * 128 + k, acc);
}

// transpose [256][256]: o[n][k] = W[k][n], bf16 hi/lo
__global__ void k_transw(const float* __restrict__ W,
                         __nv_bfloat16* __restrict__ oh, __nv_bfloat16* __restrict__ ol) {
    __shared__ float t[32][33];
    int bx = blockIdx.x * 32, by = blockIdx.y * 32;
    int tx = threadIdx.x, ty = threadIdx.y;
#pragma unroll
    for (int i = 0; i < 32; i += 8)
        t[ty + i][tx] = W[(size_t)(by + ty + i) * 256 + bx + tx];
    __syncthreads();
#pragma unroll
    for (int i = 0; i < 32; i += 8) {
        float v = t[tx][ty + i];
        split_store(oh, ol, (size_t)(bx + ty + i) * 256 + by + tx, v);
    }
}

// ---------------- GEMM ----------------
// out[M,256] = A0[M,K0] @ B0^T + A1[M,K1] @ B1^T + b0 (+b1), opt sigmoid.
// B given as [256][K] bf16 hi/lo. On sm_103a: tcgen05 SS-mode bf16 3-term split,
// tiles M=128 x N=2x128 x Kc=64, D in TMEM (256 cols fp32).
// Otherwise: fp32 FFMA fallback (same launch geometry).
#define GSMEM 100352
__global__ __launch_bounds__(256) void k_tgemm(
    const float* __restrict__ A0, const __nv_bfloat16* __restrict__ B0h,
    const __nv_bfloat16* __restrict__ B0l, int K0,
    const float* __restrict__ A1, const __nv_bfloat16* __restrict__ B1h,
    const __nv_bfloat16* __restrict__ B1l, int K1,
    const float* __restrict__ b0, const float* __restrict__ b1,
    float* __restrict__ out, int M, int act) {
    extern __shared__ char smem[];
    int tid = threadIdx.x, wid = tid >> 5, lane = tid & 31;
    int m0 = blockIdx.x * 128;

#if HAS_TCGEN05
    uint32_t sb = smem_u32(smem);
    uint32_t ctrl = sb;                              // [ctrl]=tmem ptr, [ctrl+8]=mbar
    uint32_t tiles = (sb + 16 + 1023) & ~1023u;      // 1024-aligned tile base
    uint32_t sAh = tiles, sAl = tiles + 16384, sBh = tiles + 32768, sBl = tiles + 65536;
    char* tp = smem + (tiles - sb);
    char* pAh = tp;  char* pAl = tp + 16384;  char* pBh = tp + 32768;  char* pBl = tp + 65536;

    if (tid == 0) MBARRIER_INIT(ctrl + 8, 1);
    if (wid == 0) TCGEN05_ALLOC(ctrl, 256);
    __syncthreads();
    uint32_t tb;
    asm volatile("ld.shared.b32 %0, [%1];" : "=r"(tb) : "r"(ctrl));
    if (wid == 0) TCGEN05_RELINQ();

    int chunk = 0;
#pragma unroll 1
    for (int ph = 0; ph < 2; ph++) {
        const float* A = ph ? A1 : A0;
        const __nv_bfloat16* Bh = ph ? B1h : B0h;
        const __nv_bfloat16* Bl = ph ? B1l : B0l;
        int K = ph ? K1 : K0;
#pragma unroll 1
        for (int kk = 0; kk < K; kk += 64) {
            // ---- A tile: 128 rows x 64 fp32 -> bf16 hi/lo, SW128 ----
#pragma unroll
            for (int i = 0; i < 8; i++) {
                int f = i * 256 + tid;
                int row = f >> 4, c4 = f & 15;
                float4 v = make_float4(0.f, 0.f, 0.f, 0.f);
                if (m0 + row < M)
                    v = *(const float4*)(A + (size_t)(m0 + row) * K + kk + c4 * 4);
                __nv_bfloat16 hx = __float2bfloat16_rn(v.x);
                __nv_bfloat16 hy = __float2bfloat16_rn(v.y);
                __nv_bfloat16 hz = __float2bfloat16_rn(v.z);
                __nv_bfloat16 hw = __float2bfloat16_rn(v.w);
                __nv_bfloat162 h01 = __halves2bfloat162(hx, hy);
                __nv_bfloat162 h23 = __halves2bfloat162(hz, hw);
                __nv_bfloat162 l01 = __floats2bfloat162_rn(v.x - __bfloat162float(hx),
                                                           v.y - __bfloat162float(hy));
                __nv_bfloat162 l23 = __floats2bfloat162_rn(v.z - __bfloat162float(hz),
                                                           v.w - __bfloat162float(hw));
                uint32_t off = (uint32_t)(row * 128 + c4 * 8);
                uint32_t sw = off ^ ((off >> 3) & 0x70);
                uint2 hv, lv;
                hv.x = *(uint32_t*)&h01; hv.y = *(uint32_t*)&h23;
                lv.x = *(uint32_t*)&l01; lv.y = *(uint32_t*)&l23;
                *(uint2*)(pAh + sw) = hv;
                *(uint2*)(pAl + sw) = lv;
            }
            // ---- B tiles: 256 rows x 64 bf16 (hi and lo), SW128 ----
#pragma unroll
            for (int i = 0; i < 8; i++) {
                int f = i * 256 + tid;
                int row = f >> 3, c = f & 7;
                size_t g = (size_t)row * K + kk + c * 8;
                uint4 vh = *(const uint4*)(Bh + g);
                uint4 vl = *(const uint4*)(Bl + g);
                uint32_t off = (uint32_t)(row * 128 + c * 16);
                uint32_t sw = off ^ ((off >> 3) & 0x70);
                *(uint4*)(pBh + sw) = vh;
                *(uint4*)(pBl + sw) = vl;
            }
            __syncthreads();
            if (wid == 0 && elect_one_pred()) {
                FENCE_PROXY_ASYNC();
                uint64_t dAh = MAKE_SMEM_DESC(sAh), dAl = MAKE_SMEM_DESC(sAl);
                uint64_t dBh = MAKE_SMEM_DESC(sBh), dBl = MAKE_SMEM_DESC(sBl);
#pragma unroll
                for (int nh = 0; nh < 2; nh++) {
                    uint32_t d = tb + nh * 128;
                    uint64_t bh = dBh + nh * 1024, blo = dBl + nh * 1024;
#pragma unroll
                    for (int ks = 0; ks < 4; ks++) {
                        bool first = (chunk == 0 && ks == 0);
                        mma_f16_ss(d, dAh + ks * 2, bh + ks * 2, !first);
                        mma_f16_ss(d, dAh + ks * 2, blo + ks * 2, true);
                        mma_f16_ss(d, dAl + ks * 2, bh + ks * 2, true);
                    }
                }
                TCGEN05_COMMIT(ctrl + 8);
            }
            MBARRIER_WAIT_PARITY(ctrl + 8, chunk & 1);
            chunk++;
        }
    }
    TCGEN05_FENCE_AFTER();
    // ---- epilogue: warps 0-3 read D (128 rows x 256 cols) ----
    if (wid < 4) {
        int m = m0 + wid * 32 + lane;
#pragma unroll 1
        for (int cb = 0; cb < 256; cb += 32) {
            uint32_t r[32];
            TCGEN05_LD_X32(r, tb + cb);
            TCGEN05_WAIT_LD();
            if (m < M) {
                float vals[32];
#pragma unroll
                for (int j = 0; j < 32; j++) {
                    float v = __uint_as_float(r[j]) + b0[cb + j];
                    if (b1) v += b1[cb + j];
                    if (act) v = 1.0f / (1.0f + __expf(-v));
                    vals[j] = v;
                }
                float4* op = (float4*)(out + (size_t)m * CC + cb);
#pragma unroll
                for (int q = 0; q < 8; q++) op[q] = ((float4*)vals)[q];
            }
        }
    }
    TCGEN05_FENCE_BEFORE();
    __syncthreads();
    if (wid == 0) TCGEN05_DEALLOC(tb, 256);

#else  // ---------------- FFMA fallback (plain sm_103 pass) ----------------
    float* As = (float*)smem;              // [16][128]
    float* Bs = (float*)(smem + 8192);     // [16][128]
    int tx = tid & 15, ty = tid >> 4;

#pragma unroll 1
    for (int nh = 0; nh < 2; nh++) {
        int n0 = nh * 128;
        float acc[8][8];
#pragma unroll
        for (int i = 0; i < 8; i++)
#pragma unroll
            for (int j = 0; j < 8; j++) acc[i][j] = 0.f;

#pragma unroll 1
        for (int ph = 0; ph < 2; ph++) {
            const float* A = ph ? A1 : A0;
            const __nv_bfloat16* Bh = ph ? B1h : B0h;
            const __nv_bfloat16* Bl = ph ? B1l : B0l;
            int K = ph ? K1 : K0;
#pragma unroll 1
            for (int kk = 0; kk < K; kk += 16) {
                // A tile transposed: As[k][m]
#pragma unroll
                for (int l = 0; l < 2; l++) {
                    int f4 = tid * 2 + l;
                    int row = f4 >> 2, c4 = f4 & 3;
                    float4 v = make_float4(0.f, 0.f, 0.f, 0.f);
                    if (m0 + row < M)
                        v = *(const float4*)(A + (size_t)(m0 + row) * K + kk + c4 * 4);
                    As[(c4 * 4 + 0) * 128 + row] = v.x;
                    As[(c4 * 4 + 1) * 128 + row] = v.y;
                    As[(c4 * 4 + 2) * 128 + row] = v.z;
                    As[(c4 * 4 + 3) * 128 + row] = v.w;
                }
                // B tile: Bs[k][n] = Bh[n][k] + Bl[n][k]
#pragma unroll
                for (int i = 0; i < 8; i++) {
                    int f = i * 256 + tid;
                    int n = f >> 4, kx = f & 15;
                    size_t g = (size_t)(n0 + n) * K + kk + kx;
                    float v = __bfloat162float(Bh[g]) + __bfloat162float(Bl[g]);
                    Bs[kx * 128 + n] = v;
                }
                __syncthreads();
#pragma unroll
                for (int k = 0; k < 16; k++) {
                    float a[8], b[8];
                    *(float4*)(a)     = *(float4*)&As[k * 128 + ty * 8];
                    *(float4*)(a + 4) = *(float4*)&As[k * 128 + ty * 8 + 4];
                    *(float4*)(b)     = *(float4*)&Bs[k * 128 + tx * 8];
                    *(float4*)(b + 4) = *(float4*)&Bs[k * 128 + tx * 8 + 4];
#pragma unroll
                    for (int i = 0; i < 8; i++)
#pragma unroll
                        for (int j = 0; j < 8; j++) acc[i][j] += a[i] * b[j];
                }
                __syncthreads();
            }
        }

        float bias[8];
#pragma unroll
        for (int j = 0; j < 8; j++) {
            int c = n0 + tx * 8 + j;
            float bv = b0[c];
            if (b1) bv += b1[c];
            bias[j] = bv;
        }
#pragma unroll
        for (int i = 0; i < 8; i++) {
            int gr = m0 + ty * 8 + i;
            if (gr >= M) continue;
            float vals[8];
#pragma unroll
            for (int j = 0; j < 8; j++) {
                float v = acc[i][j] + bias[j];
                if (act) v = 1.0f / (1.0f + __expf(-v));
                vals[j] = v;
            }
            float* op = out + (size_t)gr * CC + n0 + tx * 8;
            *(float4*)(op)     = *(float4*)(vals);
            *(float4*)(op + 4) = *(float4*)(vals + 4);
        }
        __syncthreads();
    }
#endif
}

// ---------------- host orchestration ----------------
extern "C" void kernel_launch(void* const* d_in, const int* in_sizes, int n_in,
                              void* d_out, int out_size) {
    const float* x_A    = (const float*)d_in[0];
    const float* x_B    = (const float*)d_in[1];
    const int*   e_ab   = (const int*)d_in[4];
    const int*   e_ba   = (const int*)d_in[5];
    const float* lin_A  = (const float*)d_in[6];
    const float* lin_B  = (const float*)d_in[7];
    const float* bias_A = (const float*)d_in[8];
    const float* bias_B = (const float*)d_in[9];
    const float* Wl_ab0 = (const float*)d_in[10];
    const float* bl_ab0 = (const float*)d_in[11];
    const float* Wr_ab0 = (const float*)d_in[12];
    const float* Wl_ba0 = (const float*)d_in[13];
    const float* bl_ba0 = (const float*)d_in[14];
    const float* Wr_ba0 = (const float*)d_in[15];
    const float* Wl_ab1 = (const float*)d_in[16];
    const float* bl_ab1 = (const float*)d_in[17];
    const float* Wr_ab1 = (const float*)d_in[18];
    const float* Wl_ba1 = (const float*)d_in[19];
    const float* bl_ba1 = (const float*)d_in[20];
    const float* Wr_ba1 = (const float*)d_in[21];
    float* out = (float*)d_out;

    int *deg, *off, *cur, *esrc, *tot;
    float *inv, *mx, *h1, *m1;
    __nv_bfloat16 *w0, *w1;
    cudaGetSymbolAddress((void**)&deg, g_deg);
    cudaGetSymbolAddress((void**)&off, g_off);
    cudaGetSymbolAddress((void**)&cur, g_cur);
    cudaGetSymbolAddress((void**)&inv, g_inv);
    cudaGetSymbolAddress((void**)&tot, g_tot);
    cudaGetSymbolAddress((void**)&esrc, g_esrc);
    cudaGetSymbolAddress((void**)&mx, g_mx);
    cudaGetSymbolAddress((void**)&h1, g_h1);
    cudaGetSymbolAddress((void**)&m1, g_m1);
    cudaGetSymbolAddress((void**)&w0, g_w0);
    cudaGetSymbolAddress((void**)&w1, g_w1);

    int* deg0 = deg;      int* deg1 = deg + NN;
    int* off0 = off;      int* off1 = off + NN;
    int* cur0 = cur;      int* cur1 = cur + NN;
    float* inv0 = inv;    float* inv1 = inv + NN;
    int* esrc0 = esrc;    int* esrc1 = esrc + EE;
    float* mx0 = mx;      float* mx1 = mx + (size_t)NN * FF;
    float* h1A = h1;      float* h1B = h1 + (size_t)NN * CC;
    float* m1A = m1;      float* m1B = m1 + (size_t)NN * CC;
    const size_t W0SZ = 256 * 128, W1SZ = 256 * 256;
    __nv_bfloat16* w0p[4][2];
    __nv_bfloat16* w1p[4][2];
    for (int i = 0; i < 4; i++)
        for (int j = 0; j < 2; j++) {
            w0p[i][j] = w0 + (2 * i + j) * W0SZ;
            w1p[i][j] = w1 + (2 * i + j) * W1SZ;
        }

    cudaFuncSetAttribute(k_tgemm, cudaFuncAttributeMaxDynamicSharedMemorySize, GSMEM);

    const int TB = 256;
    int gE = (EE + TB - 1) / TB;
    int gAgg = (NN * 32 + TB - 1) / TB;
    int gM = (NN + 127) / 128;
    dim3 tT(32, 8), gT(8, 8);

    // CSR build (type 0 = ba edges -> dst A, type 1 = ab edges -> dst B)
    cudaMemsetAsync(deg, 0, 2 * NN * sizeof(int), 0);
    cudaMemsetAsync(tot, 0, 2 * sizeof(int), 0);
    k_count<<<gE, TB>>>(e_ba + EE, deg0);
    k_count<<<gE, TB>>>(e_ab + EE, deg1);
    k_alloc<<<(2 * NN + TB - 1) / TB, TB>>>();
    k_fill<<<gE, TB>>>(e_ba, e_ba + EE, cur0, esrc0);
    k_fill<<<gE, TB>>>(e_ab, e_ab + EE, cur1, esrc1);

    // weight prep: fused layer-0 weights (transposed bf16 hi/lo) + layer-1 transposes
    k_fusew<<<128, 256>>>(lin_B, Wl_ba0, w0p[0][0], w0p[0][1]);
    k_fusew<<<128, 256>>>(lin_A, Wr_ba0, w0p[1][0], w0p[1][1]);
    k_fusew<<<128, 256>>>(lin_A, Wl_ab0, w0p[2][0], w0p[2][1]);
    k_fusew<<<128, 256>>>(lin_B, Wr_ab0, w0p[3][0], w0p[3][1]);
    k_transw<<<gT, tT>>>(Wl_ba1, w1p[0][0], w1p[0][1]);
    k_transw<<<gT, tT>>>(Wr_ba1, w1p[1][0], w1p[1][1]);
    k_transw<<<gT, tT>>>(Wl_ab1, w1p[2][0], w1p[2][1]);
    k_transw<<<gT, tT>>>(Wr_ab1, w1p[3][0], w1p[3][1]);

    // layer-0 aggregation at 128 dims (raw features)
    k_agg<128><<<gAgg, TB>>>(x_B, esrc0, off0, deg0, inv0, mx0);
    k_agg<128><<<gAgg, TB>>>(x_A, esrc1, off1, deg1, inv1, mx1);

    // layer 0: h1A = mx0@wf0^T + x_A@wf1^T + bl_ba0
    k_tgemm<<<gM, TB, GSMEM>>>(mx0, w0p[0][0], w0p[0][1], FF,
                               x_A, w0p[1][0], w0p[1][1], FF,
                               bl_ba0, nullptr, h1A, NN, 0);
    k_tgemm<<<gM, TB, GSMEM>>>(mx1, w0p[2][0], w0p[2][1], FF,
                               x_B, w0p[3][0], w0p[3][1], FF,
                               bl_ab0, nullptr, h1B, NN, 0);

    // layer-1 aggregation at 256 dims
    k_agg<256><<<gAgg, TB>>>(h1B, esrc0, off0, deg0, inv0, m1A);
    k_agg<256><<<gAgg, TB>>>(h1A, esrc1, off1, deg1, inv1, m1B);

    // layer 1 + final bias + sigmoid -> d_out
    k_tgemm<<<gM, TB, GSMEM>>>(m1A, w1p[0][0], w1p[0][1], CC,
                               h1A, w1p[1][0], w1p[1][1], CC,
                               bl_ba1, bias_A, out, NN, 1);
    k_tgemm<<<gM, TB, GSMEM>>>(m1B, w1p[2][0], w1p[2][1], CC,
                               h1B, w1p[3][0], w1p[3][1], CC,
                               bl_ab1, bias_B, out + (size_t)NN * CC, NN, 1);
}

// round 4
// speedup vs baseline: 1.9822x; 1.0604x over previous
#include <cuda_runtime.h>
#include <cuda_bf16.h>
#include <cstdint>
#include <math.h>

#define NN 100000
#define EE 1600000
#define FF 128
#define CC 256

// Detect whether this device-compilation pass has tcgen05 (sm_103a/sm_100a or family target).
#if defined(__CUDA_ARCH_FEAT_SM103_ALL) || defined(__CUDA_ARCH_FEAT_SM100_ALL)
#define HAS_TCGEN05 1
#elif defined(__CUDA_ARCH_SPECIFIC__) && (__CUDA_ARCH_SPECIFIC__ >= 1000)
#define HAS_TCGEN05 1
#elif defined(__CUDA_ARCH_FAMILY_SPECIFIC__) && (__CUDA_ARCH_FAMILY_SPECIFIC__ >= 1000)
#define HAS_TCGEN05 1
#else
#define HAS_TCGEN05 0
#endif

// ---------------- static scratch (no allocations allowed) ----------------
__device__ int   g_deg[2][NN];
__device__ int   g_off[2][NN];
__device__ int   g_cur[2][NN];
__device__ float g_inv[2][NN];
__device__ int   g_tot[2];
__device__ int   g_esrc[2][EE];
__device__ float g_mx[2][(size_t)NN * FF];     // layer-0 means (128-d)
__device__ float g_h1[2][(size_t)NN * CC];     // layer-0 outputs A1,B1 (fp32)
__device__ float g_m1[2][(size_t)NN * CC];     // layer-1 means (256-d)
__device__ __nv_bfloat162 g_xb[2][(size_t)NN * FF / 2];   // bf16 copy of x
__device__ __nv_bfloat162 g_h1b[2][(size_t)NN * CC / 2];  // bf16 copy of h1
// transposed + bf16 hi/lo split weights, [N][K] K-major
__device__ __nv_bfloat16 g_w0[4][2][256 * 128];  // layer-0 fused weights (K=128)
__device__ __nv_bfloat16 g_w1[4][2][256 * 256];  // layer-1 weights (K=256)

// ================= PTX helpers =================
__device__ __forceinline__ uint32_t smem_u32(const void* p) {
    uint32_t a;
    asm("{ .reg .u64 t; cvta.to.shared.u64 t, %1; cvt.u32.u64 %0, t; }"
        : "=r"(a) : "l"(p));
    return a;
}

#if HAS_TCGEN05
__device__ __forceinline__ uint32_t elect_one_pred() {
    uint32_t p;
    asm volatile("{\n\t.reg .pred p;\n\telect.sync _|p, 0xFFFFFFFF;\n\t"
                 "selp.b32 %0, 1, 0, p;\n\t}" : "=r"(p));
    return p;
}
#define MBARRIER_INIT(a, c) \
    asm volatile("mbarrier.init.shared.b64 [%0], %1;" :: "r"((uint32_t)(a)), "r"((uint32_t)(c)) : "memory")
#define MBARRIER_WAIT_PARITY(a, ph) do { \
    uint32_t _m = (uint32_t)(a), _p = (uint32_t)(ph), _d; \
    asm volatile("{\n\t.reg .pred p;\n\t" \
        "mbarrier.try_wait.parity.acquire.cta.shared::cta.b64 p, [%1], %2;\n\t" \
        "selp.b32 %0, 1, 0, p;\n\t}" : "=r"(_d) : "r"(_m), "r"(_p) : "memory"); \
    if (!_d) { \
        asm volatile("{\n\t.reg .pred P1;\n\tWL_%=:\n\t" \
            "mbarrier.try_wait.parity.acquire.cta.shared::cta.b64 P1, [%0], %1, 0x989680;\n\t" \
            "@P1 bra.uni WD_%=;\n\tbra.uni WL_%=;\n\tWD_%=:\n\t}" \
            :: "r"(_m), "r"(_p) : "memory"); \
    } } while (0)
#define TCGEN05_ALLOC(sa, n) \
    asm volatile("tcgen05.alloc.cta_group::1.sync.aligned.shared::cta.b32 [%0], %1;" \
                 :: "r"((uint32_t)(sa)), "r"((uint32_t)(n)) : "memory")
#define TCGEN05_DEALLOC(t, n) \
    asm volatile("tcgen05.dealloc.cta_group::1.sync.aligned.b32 %0, %1;" :: "r"(t), "r"((uint32_t)(n)))
#define TCGEN05_RELINQ() \
    asm volatile("tcgen05.relinquish_alloc_permit.cta_group::1.sync.aligned;")
#define TCGEN05_COMMIT(a) \
    asm volatile("tcgen05.commit.cta_group::1.mbarrier::arrive::one.shared::cluster.b64 [%0];" \
                 :: "r"((uint32_t)(a)) : "memory")
#define TCGEN05_FENCE_AFTER() asm volatile("tcgen05.fence::after_thread_sync;" ::: "memory")
#define TCGEN05_FENCE_BEFORE() asm volatile("tcgen05.fence::before_thread_sync;" ::: "memory")
#define TCGEN05_WAIT_LD() asm volatile("tcgen05.wait::ld.sync.aligned;" ::: "memory")
#define FENCE_PROXY_ASYNC() asm volatile("fence.proxy.async.shared::cta;" ::: "memory")
#define TCGEN05_LD_X32(r, a) \
    asm volatile("tcgen05.ld.sync.aligned.32x32b.x32.b32 " \
        "{%0, %1, %2, %3, %4, %5, %6, %7, %8, %9, %10, %11, %12, %13, %14, %15, " \
        "%16, %17, %18, %19, %20, %21, %22, %23, %24, %25, %26, %27, %28, %29, %30, %31}, [%32];" \
        : "=r"((r)[0]), "=r"((r)[1]), "=r"((r)[2]), "=r"((r)[3]), "=r"((r)[4]), "=r"((r)[5]), \
          "=r"((r)[6]), "=r"((r)[7]), "=r"((r)[8]), "=r"((r)[9]), "=r"((r)[10]), "=r"((r)[11]), \
          "=r"((r)[12]), "=r"((r)[13]), "=r"((r)[14]), "=r"((r)[15]), "=r"((r)[16]), "=r"((r)[17]), \
          "=r"((r)[18]), "=r"((r)[19]), "=r"((r)[20]), "=r"((r)[21]), "=r"((r)[22]), "=r"((r)[23]), \
          "=r"((r)[24]), "=r"((r)[25]), "=r"((r)[26]), "=r"((r)[27]), "=r"((r)[28]), "=r"((r)[29]), \
          "=r"((r)[30]), "=r"((r)[31]) : "r"(a))

static constexpr uint64_t SMEM_DESC_BASE_SW128 =
    (uint64_t(2) << 61) | (uint64_t(1) << 46) | (uint64_t(64) << 32) | (uint64_t(1) << 16);
#define MAKE_SMEM_DESC(a) (SMEM_DESC_BASE_SW128 | ((uint64_t)((a) >> 4) & 0x3FFF))

// idesc kind::f16: dtype=F32(1<<4), atype=BF16(1<<7), btype=BF16(1<<10), N=128, M=128
#define IDESC ((1u << 4) | (1u << 7) | (1u << 10) | (16u << 17) | (8u << 24))

__device__ __forceinline__ void mma_f16_ss(uint32_t d, uint64_t ad, uint64_t bd, bool acc) {
    uint32_t en = acc ? 1u : 0u, z = 0u;
    asm volatile("{\n\t.reg .pred p;\n\tsetp.ne.u32 p, %5, 0;\n\t"
        "tcgen05.mma.cta_group::1.kind::f16 [%0], %1, %2, %3, {%4, %4, %4, %4}, p;\n\t}"
        :: "r"(d), "l"(ad), "l"(bd), "r"(IDESC), "r"(z), "r"(en) : "memory");
}
#endif  // HAS_TCGEN05

// ---------------- CSR build (both edge types in one launch) ----------------
__global__ void k_count2(const int* __restrict__ d0, const int* __restrict__ d1) {
    int i = blockIdx.x * blockDim.x + threadIdx.x;
    if (i < EE) atomicAdd(&g_deg[0][d0[i]], 1);
    else if (i < 2 * EE) atomicAdd(&g_deg[1][d1[i - EE]], 1);
}
// order-free offset allocation (mean aggregation is order-invariant)
__global__ void k_alloc() {
    int i = blockIdx.x * blockDim.x + threadIdx.x;
    if (i >= 2 * NN) return;
    int t = i / NN, j = i - t * NN;
    int d = g_deg[t][j];
    int o = atomicAdd(&g_tot[t], d);
    g_off[t][j] = o;
    g_cur[t][j] = o;
    g_inv[t][j] = (d > 0) ? 1.0f / (float)d : 0.0f;
}
__global__ void k_fill2(const int* __restrict__ s0, const int* __restrict__ d0,
                        const int* __restrict__ s1, const int* __restrict__ d1) {
    int i = blockIdx.x * blockDim.x + threadIdx.x;
    if (i < EE) {
        int p = atomicAdd(&g_cur[0][d0[i]], 1);
        g_esrc[0][p] = s0[i];
    } else if (i < 2 * EE) {
        int j = i - EE;
        int p = atomicAdd(&g_cur[1][d1[j]], 1);
        g_esrc[1][p] = s1[j];
    }
}

// ---------------- fp32 -> bf16 pack of x_A / x_B ----------------
__global__ void k_cvt(const float* __restrict__ x0, const float* __restrict__ x1) {
    const size_t n = (size_t)NN * FF / 2;
    size_t i = (size_t)blockIdx.x * blockDim.x + threadIdx.x;
    if (i < n) {
        float2 v = ((const float2*)x0)[i];
        g_xb[0][i] = __floats2bfloat162_rn(v.x, v.y);
    } else if (i < 2 * n) {
        float2 v = ((const float2*)x1)[i - n];
        g_xb[1][i - n] = __floats2bfloat162_rn(v.x, v.y);
    }
}

// ---------------- segment mean gather, bf16 source (warp per dst node) ----
// grid.y = edge type t (0: ->A via ba, 1: ->B via ab)
template <int DIM>
__global__ void k_aggb(const __nv_bfloat162* __restrict__ f0,
                       const __nv_bfloat162* __restrict__ f1,
                       float* __restrict__ o0, float* __restrict__ o1) {
    int w = (blockIdx.x * blockDim.x + threadIdx.x) >> 5;
    if (w >= NN) return;
    int t = blockIdx.y;
    const __nv_bfloat162* feat = t ? f1 : f0;
    float* out = t ? o1 : o0;
    int lane = threadIdx.x & 31;
    const int V = DIM / 64;  // bf162 pairs handled per lane as uint32 words
    // per lane: V x bf162 (V*2 floats), rows are DIM/2 bf162 wide
    float acc[2 * V];
#pragma unroll
    for (int v = 0; v < 2 * V; v++) acc[v] = 0.f;
    int s0 = g_off[t][w], d = g_deg[t][w];
    int k = 0;
    for (; k + 2 <= d; k += 2) {
        int sA = g_esrc[t][s0 + k], sB = g_esrc[t][s0 + k + 1];
        const __nv_bfloat162* ra = feat + (size_t)sA * (DIM / 2) + lane * V;
        const __nv_bfloat162* rb = feat + (size_t)sB * (DIM / 2) + lane * V;
        __nv_bfloat162 av[V], bv[V];
        if (V == 2) {
            *(uint2*)av = *(const uint2*)ra;
            *(uint2*)bv = *(const uint2*)rb;
        } else {
            *(uint4*)av = *(const uint4*)ra;
            *(uint4*)bv = *(const uint4*)rb;
        }
#pragma unroll
        for (int v = 0; v < V; v++) {
            float2 a = __bfloat1622float2(av[v]);
            float2 b = __bfloat1622float2(bv[v]);
            acc[2 * v] += a.x + b.x;
            acc[2 * v + 1] += a.y + b.y;
        }
    }
    if (k < d) {
        int sA = g_esrc[t][s0 + k];
        const __nv_bfloat162* ra = feat + (size_t)sA * (DIM / 2) + lane * V;
        __nv_bfloat162 av[V];
        if (V == 2) *(uint2*)av = *(const uint2*)ra;
        else        *(uint4*)av = *(const uint4*)ra;
#pragma unroll
        for (int v = 0; v < V; v++) {
            float2 a = __bfloat1622float2(av[v]);
            acc[2 * v] += a.x;
            acc[2 * v + 1] += a.y;
        }
    }
    float iv = g_inv[t][w];
#pragma unroll
    for (int v = 0; v < 2 * V; v++) acc[v] *= iv;
    float* op = out + (size_t)w * DIM + lane * 2 * V;
    if (V == 2) {
        *(float4*)op = *(float4*)acc;
    } else {
        *(float4*)op = *(float4*)acc;
        *(float4*)(op + 4) = *(float4*)(acc + 4);
    }
}

// ---------------- weight prep ----------------
__device__ __forceinline__ void split_store(__nv_bfloat16* oh, __nv_bfloat16* ol,
                                            size_t idx, float v) {
    __nv_bfloat16 h = __float2bfloat16_rn(v);
    float r = v - __bfloat162float(h);
    oh[idx] = h;
    ol[idx] = __float2bfloat16_rn(r);
}

// wfT[n][k] = sum_c lin[k][c] * W[c][n], output [256][128] bf16 hi/lo
__global__ void k_fusew(const float* __restrict__ lin, const float* __restrict__ W,
                        __nv_bfloat16* __restrict__ oh, __nv_bfloat16* __restrict__ ol) {
    int k = blockIdx.x;        // 0..127
    int n = threadIdx.x;       // 0..255
    __shared__ float lk[256];
    lk[n] = lin[k * 256 + n];
    __syncthreads();
    float acc = 0.f;
#pragma unroll 8
    for (int c = 0; c < 256; c++) acc += lk[c] * W[c * 256 + n];
    split_store(oh, ol, (size_t)n * 128 + k, acc);
}

// transpose [256][256]: o[n][k] = W[k][n], bf16 hi/lo
__global__ void k_transw(const float* __restrict__ W,
                         __nv_bfloat16* __restrict__ oh, __nv_bfloat16* __restrict__ ol) {
    __shared__ float t[32][33];
    int bx = blockIdx.x * 32, by = blockIdx.y * 32;
    int tx = threadIdx.x, ty = threadIdx.y;
#pragma unroll
    for (int i = 0; i < 32; i += 8)
        t[ty + i][tx] = W[(size_t)(by + ty + i) * 256 + bx + tx];
    __syncthreads();
#pragma unroll
    for (int i = 0; i < 32; i += 8) {
        float v = t[tx][ty + i];
        split_store(oh, ol, (size_t)(bx + ty + i) * 256 + by + tx, v);
    }
}

// ---------------- GEMM ----------------
// out[M,256] = A0[M,K0] @ B0^T + A1[M,K1] @ B1^T + b0 (+b1), opt sigmoid.
// B given as [256][K] bf16 hi/lo. On sm_103a: tcgen05 SS-mode bf16 3-term split,
// tiles M=128 x N=2x128 x Kc=64, D in TMEM (256 cols fp32).
// outb (optional): packed bf16 copy of the (pre-activation) output.
#define GSMEM 100352
__global__ __launch_bounds__(256) void k_tgemm(
    const float* __restrict__ A0, const __nv_bfloat16* __restrict__ B0h,
    const __nv_bfloat16* __restrict__ B0l, int K0,
    const float* __restrict__ A1, const __nv_bfloat16* __restrict__ B1h,
    const __nv_bfloat16* __restrict__ B1l, int K1,
    const float* __restrict__ b0, const float* __restrict__ b1,
    float* __restrict__ out, __nv_bfloat162* __restrict__ outb, int M, int act) {
    extern __shared__ char smem[];
    int tid = threadIdx.x, wid = tid >> 5, lane = tid & 31;
    int m0 = blockIdx.x * 128;

#if HAS_TCGEN05
    uint32_t sb = smem_u32(smem);
    uint32_t ctrl = sb;                              // [ctrl]=tmem ptr, [ctrl+8]=mbar
    uint32_t tiles = (sb + 16 + 1023) & ~1023u;      // 1024-aligned tile base
    uint32_t sAh = tiles, sAl = tiles + 16384, sBh = tiles + 32768, sBl = tiles + 65536;
    char* tp = smem + (tiles - sb);
    char* pAh = tp;  char* pAl = tp + 16384;  char* pBh = tp + 32768;  char* pBl = tp + 65536;

    if (tid == 0) MBARRIER_INIT(ctrl + 8, 1);
    if (wid == 0) TCGEN05_ALLOC(ctrl, 256);
    __syncthreads();
    uint32_t tb;
    asm volatile("ld.shared.b32 %0, [%1];" : "=r"(tb) : "r"(ctrl));
    if (wid == 0) TCGEN05_RELINQ();

    int chunk = 0;
#pragma unroll 1
    for (int ph = 0; ph < 2; ph++) {
        const float* A = ph ? A1 : A0;
        const __nv_bfloat16* Bh = ph ? B1h : B0h;
        const __nv_bfloat16* Bl = ph ? B1l : B0l;
        int K = ph ? K1 : K0;
#pragma unroll 1
        for (int kk = 0; kk < K; kk += 64) {
            // ---- A tile: 128 rows x 64 fp32 -> bf16 hi/lo, SW128 ----
#pragma unroll
            for (int i = 0; i < 8; i++) {
                int f = i * 256 + tid;
                int row = f >> 4, c4 = f & 15;
                float4 v = make_float4(0.f, 0.f, 0.f, 0.f);
                if (m0 + row < M)
                    v = *(const float4*)(A + (size_t)(m0 + row) * K + kk + c4 * 4);
                __nv_bfloat16 hx = __float2bfloat16_rn(v.x);
                __nv_bfloat16 hy = __float2bfloat16_rn(v.y);
                __nv_bfloat16 hz = __float2bfloat16_rn(v.z);
                __nv_bfloat16 hw = __float2bfloat16_rn(v.w);
                __nv_bfloat162 h01 = __halves2bfloat162(hx, hy);
                __nv_bfloat162 h23 = __halves2bfloat162(hz, hw);
                __nv_bfloat162 l01 = __floats2bfloat162_rn(v.x - __bfloat162float(hx),
                                                           v.y - __bfloat162float(hy));
                __nv_bfloat162 l23 = __floats2bfloat162_rn(v.z - __bfloat162float(hz),
                                                           v.w - __bfloat162float(hw));
                uint32_t off = (uint32_t)(row * 128 + c4 * 8);
                uint32_t sw = off ^ ((off >> 3) & 0x70);
                uint2 hv, lv;
                hv.x = *(uint32_t*)&h01; hv.y = *(uint32_t*)&h23;
                lv.x = *(uint32_t*)&l01; lv.y = *(uint32_t*)&l23;
                *(uint2*)(pAh + sw) = hv;
                *(uint2*)(pAl + sw) = lv;
            }
            // ---- B tiles: 256 rows x 64 bf16 (hi and lo), SW128 ----
#pragma unroll
            for (int i = 0; i < 8; i++) {
                int f = i * 256 + tid;
                int row = f >> 3, c = f & 7;
                size_t g = (size_t)row * K + kk + c * 8;
                uint4 vh = *(const uint4*)(Bh + g);
                uint4 vl = *(const uint4*)(Bl + g);
                uint32_t off = (uint32_t)(row * 128 + c * 16);
                uint32_t sw = off ^ ((off >> 3) & 0x70);
                *(uint4*)(pBh + sw) = vh;
                *(uint4*)(pBl + sw) = vl;
            }
            __syncthreads();
            if (wid == 0 && elect_one_pred()) {
                FENCE_PROXY_ASYNC();
                uint64_t dAh = MAKE_SMEM_DESC(sAh), dAl = MAKE_SMEM_DESC(sAl);
                uint64_t dBh = MAKE_SMEM_DESC(sBh), dBl = MAKE_SMEM_DESC(sBl);
#pragma unroll
                for (int nh = 0; nh < 2; nh++) {
                    uint32_t d = tb + nh * 128;
                    uint64_t bh = dBh + nh * 1024, blo = dBl + nh * 1024;
#pragma unroll
                    for (int ks = 0; ks < 4; ks++) {
                        bool first = (chunk == 0 && ks == 0);
                        mma_f16_ss(d, dAh + ks * 2, bh + ks * 2, !first);
                        mma_f16_ss(d, dAh + ks * 2, blo + ks * 2, true);
                        mma_f16_ss(d, dAl + ks * 2, bh + ks * 2, true);
                    }
                }
                TCGEN05_COMMIT(ctrl + 8);
            }
            MBARRIER_WAIT_PARITY(ctrl + 8, chunk & 1);
            chunk++;
        }
    }
    TCGEN05_FENCE_AFTER();
    // ---- epilogue: warps 0-3 read D (128 rows x 256 cols) ----
    if (wid < 4) {
        int m = m0 + wid * 32 + lane;
#pragma unroll 1
        for (int cb = 0; cb < 256; cb += 32) {
            uint32_t r[32];
            TCGEN05_LD_X32(r, tb + cb);
            TCGEN05_WAIT_LD();
            if (m < M) {
                float vals[32];
#pragma unroll
                for (int j = 0; j < 32; j++) {
                    float v = __uint_as_float(r[j]) + b0[cb + j];
                    if (b1) v += b1[cb + j];
                    if (act) v = 1.0f / (1.0f + __expf(-v));
                    vals[j] = v;
                }
                float4* op = (float4*)(out + (size_t)m * CC + cb);
#pragma unroll
                for (int q = 0; q < 8; q++) op[q] = ((float4*)vals)[q];
                if (outb) {
                    __nv_bfloat162 bb[16];
#pragma unroll
                    for (int j = 0; j < 16; j++)
                        bb[j] = __floats2bfloat162_rn(vals[2 * j], vals[2 * j + 1]);
                    uint4* obp = (uint4*)(outb + (size_t)m * (CC / 2) + cb / 2);
#pragma unroll
                    for (int q = 0; q < 4; q++) obp[q] = ((uint4*)bb)[q];
                }
            }
        }
    }
    TCGEN05_FENCE_BEFORE();
    __syncthreads();
    if (wid == 0) TCGEN05_DEALLOC(tb, 256);

#else  // ---------------- FFMA fallback (plain sm_103 pass) ----------------
    float* As = (float*)smem;              // [16][128]
    float* Bs = (float*)(smem + 8192);     // [16][128]
    int tx = tid & 15, ty = tid >> 4;

#pragma unroll 1
    for (int nh = 0; nh < 2; nh++) {
        int n0 = nh * 128;
        float acc[8][8];
#pragma unroll
        for (int i = 0; i < 8; i++)
#pragma unroll
            for (int j = 0; j < 8; j++) acc[i][j] = 0.f;

#pragma unroll 1
        for (int ph = 0; ph < 2; ph++) {
            const float* A = ph ? A1 : A0;
            const __nv_bfloat16* Bh = ph ? B1h : B0h;
            const __nv_bfloat16* Bl = ph ? B1l : B0l;
            int K = ph ? K1 : K0;
#pragma unroll 1
            for (int kk = 0; kk < K; kk += 16) {
#pragma unroll
                for (int l = 0; l < 2; l++) {
                    int f4 = tid * 2 + l;
                    int row = f4 >> 2, c4 = f4 & 3;
                    float4 v = make_float4(0.f, 0.f, 0.f, 0.f);
                    if (m0 + row < M)
                        v = *(const float4*)(A + (size_t)(m0 + row) * K + kk + c4 * 4);
                    As[(c4 * 4 + 0) * 128 + row] = v.x;
                    As[(c4 * 4 + 1) * 128 + row] = v.y;
                    As[(c4 * 4 + 2) * 128 + row] = v.z;
                    As[(c4 * 4 + 3) * 128 + row] = v.w;
                }
#pragma unroll
                for (int i = 0; i < 8; i++) {
                    int f = i * 256 + tid;
                    int n = f >> 4, kx = f & 15;
                    size_t g = (size_t)(n0 + n) * K + kk + kx;
                    float v = __bfloat162float(Bh[g]) + __bfloat162float(Bl[g]);
                    Bs[kx * 128 + n] = v;
                }
                __syncthreads();
#pragma unroll
                for (int k = 0; k < 16; k++) {
                    float a[8], b[8];
                    *(float4*)(a)     = *(float4*)&As[k * 128 + ty * 8];
                    *(float4*)(a + 4) = *(float4*)&As[k * 128 + ty * 8 + 4];
                    *(float4*)(b)     = *(float4*)&Bs[k * 128 + tx * 8];
                    *(float4*)(b + 4) = *(float4*)&Bs[k * 128 + tx * 8 + 4];
#pragma unroll
                    for (int i = 0; i < 8; i++)
#pragma unroll
                        for (int j = 0; j < 8; j++) acc[i][j] += a[i] * b[j];
                }
                __syncthreads();
            }
        }

        float bias[8];
#pragma unroll
        for (int j = 0; j < 8; j++) {
            int c = n0 + tx * 8 + j;
            float bv = b0[c];
            if (b1) bv += b1[c];
            bias[j] = bv;
        }
#pragma unroll
        for (int i = 0; i < 8; i++) {
            int gr = m0 + ty * 8 + i;
            if (gr >= M) continue;
            float vals[8];
#pragma unroll
            for (int j = 0; j < 8; j++) {
                float v = acc[i][j] + bias[j];
                if (act) v = 1.0f / (1.0f + __expf(-v));
                vals[j] = v;
            }
            float* op = out + (size_t)gr * CC + n0 + tx * 8;
            *(float4*)(op)     = *(float4*)(vals);
            *(float4*)(op + 4) = *(float4*)(vals + 4);
            if (outb) {
                __nv_bfloat162 bb[4];
#pragma unroll
                for (int j = 0; j < 4; j++)
                    bb[j] = __floats2bfloat162_rn(vals[2 * j], vals[2 * j + 1]);
                uint4* obp = (uint4*)(outb + (size_t)gr * (CC / 2) + (n0 + tx * 8) / 2);
                obp[0] = *(uint4*)bb;
            }
        }
        __syncthreads();
    }
#endif
}

// ---------------- host orchestration ----------------
extern "C" void kernel_launch(void* const* d_in, const int* in_sizes, int n_in,
                              void* d_out, int out_size) {
    const float* x_A    = (const float*)d_in[0];
    const float* x_B    = (const float*)d_in[1];
    const int*   e_ab   = (const int*)d_in[4];
    const int*   e_ba   = (const int*)d_in[5];
    const float* lin_A  = (const float*)d_in[6];
    const float* lin_B  = (const float*)d_in[7];
    const float* bias_A = (const float*)d_in[8];
    const float* bias_B = (const float*)d_in[9];
    const float* Wl_ab0 = (const float*)d_in[10];
    const float* bl_ab0 = (const float*)d_in[11];
    const float* Wr_ab0 = (const float*)d_in[12];
    const float* Wl_ba0 = (const float*)d_in[13];
    const float* bl_ba0 = (const float*)d_in[14];
    const float* Wr_ba0 = (const float*)d_in[15];
    const float* Wl_ab1 = (const float*)d_in[16];
    const float* bl_ab1 = (const float*)d_in[17];
    const float* Wr_ab1 = (const float*)d_in[18];
    const float* Wl_ba1 = (const float*)d_in[19];
    const float* bl_ba1 = (const float*)d_in[20];
    const float* Wr_ba1 = (const float*)d_in[21];
    float* out = (float*)d_out;

    int *deg, *tot;
    float *mx, *h1, *m1;
    __nv_bfloat16 *w0, *w1;
    __nv_bfloat162 *xb, *h1b;
    cudaGetSymbolAddress((void**)&deg, g_deg);
    cudaGetSymbolAddress((void**)&tot, g_tot);
    cudaGetSymbolAddress((void**)&mx, g_mx);
    cudaGetSymbolAddress((void**)&h1, g_h1);
    cudaGetSymbolAddress((void**)&m1, g_m1);
    cudaGetSymbolAddress((void**)&w0, g_w0);
    cudaGetSymbolAddress((void**)&w1, g_w1);
    cudaGetSymbolAddress((void**)&xb, g_xb);
    cudaGetSymbolAddress((void**)&h1b, g_h1b);

    float* mx0 = mx;      float* mx1 = mx + (size_t)NN * FF;
    float* h1A = h1;      float* h1B = h1 + (size_t)NN * CC;
    float* m1A = m1;      float* m1B = m1 + (size_t)NN * CC;
    __nv_bfloat162* xb0 = xb;    __nv_bfloat162* xb1 = xb + (size_t)NN * FF / 2;
    __nv_bfloat162* h1bA = h1b;  __nv_bfloat162* h1bB = h1b + (size_t)NN * CC / 2;
    const size_t W0SZ = 256 * 128, W1SZ = 256 * 256;
    __nv_bfloat16* w0p[4][2];
    __nv_bfloat16* w1p[4][2];
    for (int i = 0; i < 4; i++)
        for (int j = 0; j < 2; j++) {
            w0p[i][j] = w0 + (2 * i + j) * W0SZ;
            w1p[i][j] = w1 + (2 * i + j) * W1SZ;
        }

    cudaFuncSetAttribute(k_tgemm, cudaFuncAttributeMaxDynamicSharedMemorySize, GSMEM);

    const int TB = 256;
    int g2E = (2 * EE + TB - 1) / TB;
    dim3 gAgg((NN * 32 + TB - 1) / TB, 2);
    int gM = (NN + 127) / 128;
    dim3 tT(32, 8), gT(8, 8);
    int gCvt = (int)(((size_t)NN * FF + TB - 1) / TB);  // 2*(N*F/2) threads

    // CSR build (type 0 = ba edges -> dst A, type 1 = ab edges -> dst B)
    cudaMemsetAsync(deg, 0, 2 * NN * sizeof(int), 0);
    cudaMemsetAsync(tot, 0, 2 * sizeof(int), 0);
    k_count2<<<g2E, TB>>>(e_ba + EE, e_ab + EE);
    k_alloc<<<(2 * NN + TB - 1) / TB, TB>>>();
    k_fill2<<<g2E, TB>>>(e_ba, e_ba + EE, e_ab, e_ab + EE);

    // bf16 copies of x for cheap gathering
    k_cvt<<<gCvt, TB>>>(x_A, x_B);

    // weight prep: fused layer-0 weights (transposed bf16 hi/lo) + layer-1 transposes
    k_fusew<<<128, 256>>>(lin_B, Wl_ba0, w0p[0][0], w0p[0][1]);
    k_fusew<<<128, 256>>>(lin_A, Wr_ba0, w0p[1][0], w0p[1][1]);
    k_fusew<<<128, 256>>>(lin_A, Wl_ab0, w0p[2][0], w0p[2][1]);
    k_fusew<<<128, 256>>>(lin_B, Wr_ab0, w0p[3][0], w0p[3][1]);
    k_transw<<<gT, tT>>>(Wl_ba1, w1p[0][0], w1p[0][1]);
    k_transw<<<gT, tT>>>(Wr_ba1, w1p[1][0], w1p[1][1]);
    k_transw<<<gT, tT>>>(Wl_ab1, w1p[2][0], w1p[2][1]);
    k_transw<<<gT, tT>>>(Wr_ab1, w1p[3][0], w1p[3][1]);

    // layer-0 aggregation at 128 dims (bf16 gather): t=0 reads x_B -> mx0, t=1 reads x_A -> mx1
    k_aggb<128><<<gAgg, TB>>>(xb1, xb0, mx0, mx1);

    // layer 0: h1A = mx0@wf0^T + x_A@wf1^T + bl_ba0 (+ bf16 copy for layer-1 gather)
    k_tgemm<<<gM, TB, GSMEM>>>(mx0, w0p[0][0], w0p[0][1], FF,
                               x_A, w0p[1][0], w0p[1][1], FF,
                               bl_ba0, nullptr, h1A, h1bA, NN, 0);
    k_tgemm<<<gM, TB, GSMEM>>>(mx1, w0p[2][0], w0p[2][1], FF,
                               x_B, w0p[3][0], w0p[3][1], FF,
                               bl_ab0, nullptr, h1B, h1bB, NN, 0);

    // layer-1 aggregation at 256 dims (bf16 gather): t=0 reads h1B -> m1A, t=1 reads h1A -> m1B
    k_aggb<256><<<gAgg, TB>>>(h1bB, h1bA, m1A, m1B);

    // layer 1 + final bias + sigmoid -> d_out
    k_tgemm<<<gM, TB, GSMEM>>>(m1A, w1p[0][0], w1p[0][1], CC,
                               h1A, w1p[1][0], w1p[1][1], CC,
                               bl_ba1, bias_A, out, nullptr, NN, 1);
    k_tgemm<<<gM, TB, GSMEM>>>(m1B, w1p[2][0], w1p[2][1], CC,
                               h1B, w1p[3][0], w1p[3][1], CC,
                               bl_ab1, bias_B, out + (size_t)NN * CC, nullptr, NN, 1);
}